// round 10
// baseline (speedup 1.0000x reference)
#include <cuda_runtime.h>

// Levinson-Durbin, one thread per batch (B=65536, M=64).
// R8: frequency-weighted hybrid r storage, UNCAPPED registers.
//   r[t] is read (65-t) times. r[0..31] (1552 of 2080 reads) lives in a
//   register array; r[32..64] (528 reads) is read in place from the shared
//   staging row through a VOLATILE pointer so the compiler cannot promote
//   it back to registers (which would recreate R1's 239-reg / 8-warp config).
//   State ~= 97 floats -> expect ~160-190 regs -> 5-6 CTAs/SM at BT=64
//   (10-12 warps vs R1's 8), with 75% less LDS than R7's 128-reg config.
// Body otherwise = R6/R7: negInvE off-critical-path division, 4-acc dot,
// no bounds guards (sizes divide exactly).

constexpr int M   = 64;
constexpr int NR  = M + 1;  // 65 floats per row
constexpr int BT  = 64;     // threads (= batches) per block
constexpr int RLO = 32;     // r[0..RLO-1] in registers; rest volatile-shared

__global__ __launch_bounds__(BT)
void levdur_kernel(const float* __restrict__ g_r,
                   float* __restrict__ g_out)
{
    __shared__ float sm[BT * NR];   // 16,640 B
    const int tid = threadIdx.x;
    const long long base = (long long)blockIdx.x * BT * NR;

    // Coalesced load: flat copy of this block's 64 rows (exact fit).
    #pragma unroll
    for (int i = 0; i < NR; ++i) {
        sm[i * BT + tid] = g_r[base + (long long)i * BT + tid];
    }
    __syncthreads();

    float* srow = &sm[tid * NR];               // stride 65 -> conflict-free
    const volatile float* rcold = srow;        // blocks register promotion

    {
        // Hot prefix of r in registers (compile-time indices after unroll).
        float rlo[RLO];
        #pragma unroll
        for (int i = 0; i < RLO; ++i) rlo[i] = srow[i];

        float a[NR];                 // a[1..M] register-resident
        const float r0 = rlo[0];
        float negInvE = __fdividef(-1.0f, r0);   // -1/E_0
        float P = 1.0f;                          // prod of (1 - k^2)

        // Compile-time select (folds after full unroll).
        #define RGET(i) ((i) < RLO ? rlo[(i) < RLO ? (i) : 0] : rcold[(i)])

        #pragma unroll
        for (int m = 1; m <= M; ++m) {
            // num = r[m] + sum_{j=1}^{m-1} a[j]*r[m-j], 4-way ILP split.
            float acc0 = RGET(m), acc1 = 0.0f, acc2 = 0.0f, acc3 = 0.0f;
            #pragma unroll
            for (int j = 1; j <= m - 1; ++j) {
                switch ((j - 1) & 3) {
                    case 0: acc0 = fmaf(a[j], RGET(m - j), acc0); break;
                    case 1: acc1 = fmaf(a[j], RGET(m - j), acc1); break;
                    case 2: acc2 = fmaf(a[j], RGET(m - j), acc2); break;
                    default: acc3 = fmaf(a[j], RGET(m - j), acc3); break;
                }
            }
            float num = (acc0 + acc1) + (acc2 + acc3);

            float k = num * negInvE;             // = -num / E (4-cyc path)

            // Off-critical-path refresh (hidden under update + next dot):
            float c = fmaf(-k, k, 1.0f);         // 1 - k^2
            P *= c;
            negInvE = __fdividef(negInvE, c);

            // a_new[i] = a[i] + k * a[m-i], symmetric pairs in place.
            #pragma unroll
            for (int i = 1; i < m - i; ++i) {
                float t = a[i];
                a[i]     = fmaf(k, a[m - i], t);
                a[m - i] = fmaf(k, t, a[m - i]);
            }
            if ((m & 1) == 0 && m >= 2) {        // middle element (m even)
                int h = m >> 1;
                a[h] = fmaf(k, a[h], a[h]);
            }
            a[m] = k;
        }
        #undef RGET

        // Result into our shared row: [K, a1..aM],  K = sqrt(r0 * prod c).
        srow[0] = sqrtf(r0 * P);
        #pragma unroll
        for (int i = 1; i <= M; ++i) srow[i] = a[i];
    }
    __syncthreads();

    // Coalesced store (exact fit).
    #pragma unroll
    for (int i = 0; i < NR; ++i) {
        g_out[base + (long long)i * BT + tid] = sm[i * BT + tid];
    }
}

extern "C" void kernel_launch(void* const* d_in, const int* in_sizes, int n_in,
                              void* d_out, int out_size)
{
    const float* r = (const float*)d_in[0];
    float* out = (float*)d_out;
    int nbatch = in_sizes[0] / NR;           // 65536 (exact multiple of BT)
    int grid = nbatch / BT;                  // 1024
    levdur_kernel<<<grid, BT>>>(r, out);
}

// round 11
// speedup vs baseline: 1.7905x; 1.7905x over previous
#include <cuda_runtime.h>
#include <string.h>

// Levinson-Durbin, TWO batches per thread via packed f32x2 (B=65536, M=64).
// Every scalar op of the proven R6 body becomes one fma.rn.f32x2 over the
// batch pair {A,B}: per-batch fma-pipe cost halves. r lives ONLY in shared,
// interleaved per pair: prow[c] = {rA[c], rB[c]}, row stride 130 floats
// (520B, 8B-aligned, conflict-free LDS.64: per half-wavefront lanes cover
// all 32 banks). a[] is float2 a[65] in registers with compile-time indices.
// k/E/P are per-lane scalars (small unpack per step, off critical path).
// BT=64, grid=512 -> occupancy is grid-limited (3.46 CTAs/SM), so the
// (64,4) cap (256 regs) only guards against spills and cannot reduce warps.

constexpr int M  = 64;
constexpr int NR = M + 1;     // 65
constexpr int BT = 64;        // threads per block; block covers 128 batches
constexpr int PS = 2 * NR;    // 130 floats per pair-row
constexpr int BLK_FLOATS = 2 * BT * NR;   // 8320 floats staged per block

__device__ __forceinline__ float2 ffma2(float2 a, float2 b, float2 c) {
    unsigned long long ua, ub, uc, ud;
    memcpy(&ua, &a, 8); memcpy(&ub, &b, 8); memcpy(&uc, &c, 8);
    asm("fma.rn.f32x2 %0, %1, %2, %3;" : "=l"(ud) : "l"(ua), "l"(ub), "l"(uc));
    float2 d; memcpy(&d, &ud, 8); return d;
}
__device__ __forceinline__ float2 add2(float2 a, float2 b) {
    unsigned long long ua, ub, ud;
    memcpy(&ua, &a, 8); memcpy(&ub, &b, 8);
    asm("add.rn.f32x2 %0, %1, %2;" : "=l"(ud) : "l"(ua), "l"(ub));
    float2 d; memcpy(&d, &ud, 8); return d;
}
__device__ __forceinline__ float2 mul2(float2 a, float2 b) {
    unsigned long long ua, ub, ud;
    memcpy(&ua, &a, 8); memcpy(&ub, &b, 8);
    asm("mul.rn.f32x2 %0, %1, %2;" : "=l"(ud) : "l"(ua), "l"(ub));
    float2 d; memcpy(&d, &ud, 8); return d;
}

__global__ __launch_bounds__(BT, 4)
void levdur_kernel(const float* __restrict__ g_r,
                   float* __restrict__ g_out)
{
    __shared__ __align__(16) float sm[BLK_FLOATS];   // 33,280 B
    const int tid = threadIdx.x;
    const long long gbase = (long long)blockIdx.x * BLK_FLOATS;

    // Coalesced load -> interleaved pair layout:
    //   sm[(b>>1)*130 + 2*c + (b&1)] = r_b[c]
    #pragma unroll
    for (int it = 0; it < BLK_FLOATS / BT; ++it) {
        int loc = it * BT + tid;
        float v = g_r[gbase + loc];
        int b = loc / NR;
        int c = loc - b * NR;
        sm[(b >> 1) * PS + 2 * c + (b & 1)] = v;
    }
    __syncthreads();

    float* prow = &sm[tid * PS];   // this thread's pair row (private)
    #define RLD(c) (*reinterpret_cast<const float2*>(prow + 2 * (c)))

    {
        float2 a[NR];              // a[1..64] packed {A,B}; 128 regs
        const float2 r0 = RLD(0);
        float2 negInvE = make_float2(__fdividef(-1.0f, r0.x),
                                     __fdividef(-1.0f, r0.y));
        float2 P = make_float2(1.0f, 1.0f);
        const float2 one2 = make_float2(1.0f, 1.0f);

        #pragma unroll
        for (int m = 1; m <= M; ++m) {
            // num = r[m] + sum_{j=1}^{m-1} a[j]*r[m-j], 4-acc f32x2.
            float2 acc0 = RLD(m);
            float2 acc1 = make_float2(0.f, 0.f);
            float2 acc2 = make_float2(0.f, 0.f);
            float2 acc3 = make_float2(0.f, 0.f);
            #pragma unroll
            for (int j = 1; j <= m - 1; ++j) {
                switch ((j - 1) & 3) {
                    case 0: acc0 = ffma2(a[j], RLD(m - j), acc0); break;
                    case 1: acc1 = ffma2(a[j], RLD(m - j), acc1); break;
                    case 2: acc2 = ffma2(a[j], RLD(m - j), acc2); break;
                    default: acc3 = ffma2(a[j], RLD(m - j), acc3); break;
                }
            }
            float2 num = add2(add2(acc0, acc1), add2(acc2, acc3));

            float2 k = mul2(num, negInvE);                  // -num/E per lane

            // Off-critical-path per-lane refresh of E-state:
            float2 nk = make_float2(-k.x, -k.y);
            float2 c2 = ffma2(nk, k, one2);                 // 1 - k^2
            P = mul2(P, c2);
            negInvE.x = __fdividef(negInvE.x, c2.x);
            negInvE.y = __fdividef(negInvE.y, c2.y);

            // a_new[i] = a[i] + k*a[m-i], symmetric pairs in place.
            #pragma unroll
            for (int i = 1; i < m - i; ++i) {
                float2 t = a[i];
                a[i]     = ffma2(k, a[m - i], t);
                a[m - i] = ffma2(k, t, a[m - i]);
            }
            if ((m & 1) == 0 && m >= 2) {                   // middle (m even)
                int h = m >> 1;
                a[h] = ffma2(k, a[h], a[h]);
            }
            a[m] = k;
        }

        // Results into plain row layout, entirely within this thread's own
        // 130-float region (rows 2*tid and 2*tid+1) -> no sync needed first.
        float* oA = &sm[(2 * tid) * NR];        // == prow
        float* oB = &sm[(2 * tid) * NR + NR];   // second half of prow region
        float2 Er = mul2(make_float2(r0.x, r0.y), P);       // r0 * prod(c)
        // NOTE: oA[0] overwrite happens after all RLD reads are done (a[] final).
        float kA = sqrtf(Er.x), kB = sqrtf(Er.y);
        #pragma unroll
        for (int i = M; i >= 1; --i) {          // write a's first (desc), then K
            oB[i] = a[i].y;
            oA[i] = a[i].x;
        }
        oA[0] = kA;
        oB[0] = kB;
    }
    #undef RLD
    __syncthreads();

    // Coalesced store: plain layout flat-matches the output.
    #pragma unroll
    for (int it = 0; it < BLK_FLOATS / BT; ++it) {
        int loc = it * BT + tid;
        g_out[gbase + loc] = sm[loc];
    }
}

extern "C" void kernel_launch(void* const* d_in, const int* in_sizes, int n_in,
                              void* d_out, int out_size)
{
    const float* r = (const float*)d_in[0];
    float* out = (float*)d_out;
    int nbatch = in_sizes[0] / NR;           // 65536
    int grid = nbatch / (2 * BT);            // 512 blocks x 128 batches
    levdur_kernel<<<grid, BT>>>(r, out);
}

// round 14
// speedup vs baseline: 13.4693x; 7.5225x over previous
#include <cuda_runtime.h>

// Levinson-Durbin, one thread per batch (B=65536, M=64).
// R11 = R7 shell (BT=64, launch_bounds(64,7), negInvE off-critical-path)
// with the dot product's r-reads PAIRED: one aligned LDS.64 (float2) feeds
// two scalar FFMAs via .x/.y. No packed math, no layout reversal. Row
// stride 66 floats (264B, 8B-aligned; conflict-free for 64-bit accesses).
// r[m] init term folded in as virtual a[0]=1. LDS count 2080 -> ~1088 per
// thread: halves the LDS->FFMA latency-exposure events that make up the
// measured gap between 51K cyc actual and the 29K cyc pipe floors.

constexpr int M  = 64;
constexpr int NR = M + 1;   // 65 logical floats per row
constexpr int RS = 66;      // shared row stride (264B, 8B-aligned)
constexpr int BT = 64;      // threads (= batches) per block

__global__ __launch_bounds__(BT, 7)
void levdur_kernel(const float* __restrict__ g_r,
                   float* __restrict__ g_out)
{
    __shared__ __align__(8) float sm[BT * RS];   // 16,896 B; 7 CTAs -> 118 KB
    const int tid = threadIdx.x;
    const long long gbase = (long long)blockIdx.x * (BT * NR);

    // Coalesced load -> stride-66 rows: sm[b*66 + c] = r_b[c].
    #pragma unroll
    for (int i = 0; i < NR; ++i) {
        int loc = i * BT + tid;              // 0 .. 64*65-1
        float v = g_r[gbase + loc];
        int b = loc / NR;
        int c = loc - b * NR;
        sm[b * RS + c] = v;
    }
    __syncthreads();

    float* srow = &sm[tid * RS];   // private row (8B-aligned)

    {
        float a[NR];               // a[1..M] in registers (constant indices)
        const float r0 = srow[0];
        float negInvE = __fdividef(-1.0f, r0);   // -1/E_0
        float P = 1.0f;                          // prod of (1 - k^2)

        #pragma unroll
        for (int m = 1; m <= M; ++m) {
            // num = sum_{c=1}^{m} a[m-c]*r[c]  with a[0] ≡ 1.
            // Pairs {r[2s], r[2s+1]} via one aligned LDS.64 each.
            float acc0 = 0.0f, acc1 = 0.0f, acc2 = 0.0f, acc3 = 0.0f;
            #pragma unroll
            for (int s = 0; s <= m / 2; ++s) {
                float2 v = *reinterpret_cast<const float2*>(srow + 2 * s);
                const int c0 = 2 * s, c1 = 2 * s + 1;
                if (c0 >= 1 && c0 <= m) {
                    if (c0 == m) { acc0 += v.x; }               // a[0]=1 term
                    else if (s & 1) acc2 = fmaf(a[m - c0], v.x, acc2);
                    else            acc0 = fmaf(a[m - c0], v.x, acc0);
                }
                if (c1 <= m) {
                    if (c1 == m) { acc1 += v.y; }               // a[0]=1 term
                    else if (s & 1) acc3 = fmaf(a[m - c1], v.y, acc3);
                    else            acc1 = fmaf(a[m - c1], v.y, acc1);
                }
            }
            float num = (acc0 + acc2) + (acc1 + acc3);

            float k = num * negInvE;             // = -num / E  (4-cyc path)

            // Off-critical-path refresh (hidden under update + next dot):
            float c = fmaf(-k, k, 1.0f);         // 1 - k^2
            P *= c;
            negInvE = __fdividef(negInvE, c);

            // a_new[i] = a[i] + k * a[m-i], symmetric pairs in place.
            #pragma unroll
            for (int i = 1; i < m - i; ++i) {
                float t = a[i];
                a[i]     = fmaf(k, a[m - i], t);
                a[m - i] = fmaf(k, t, a[m - i]);
            }
            if ((m & 1) == 0 && m >= 2) {        // middle element (m even)
                int h = m >> 1;
                a[h] = fmaf(k, a[h], a[h]);
            }
            a[m] = k;
        }

        // Result into our row: [K, a1..aM],  K = sqrt(r0 * prod c).
        srow[0] = sqrtf(r0 * P);
        #pragma unroll
        for (int i = 1; i <= M; ++i) srow[i] = a[i];
    }
    __syncthreads();

    // Coalesced store from stride-66 rows back to flat layout.
    #pragma unroll
    for (int i = 0; i < NR; ++i) {
        int loc = i * BT + tid;
        int b = loc / NR;
        int c = loc - b * NR;
        g_out[gbase + loc] = sm[b * RS + c];
    }
}

extern "C" void kernel_launch(void* const* d_in, const int* in_sizes, int n_in,
                              void* d_out, int out_size)
{
    const float* r = (const float*)d_in[0];
    float* out = (float*)d_out;
    int nbatch = in_sizes[0] / NR;           // 65536
    int grid = nbatch / BT;                  // 1024
    levdur_kernel<<<grid, BT>>>(r, out);
}